// round 6
// baseline (speedup 1.0000x reference)
#include <cuda_runtime.h>
#include <cstdint>

#define B_   2
#define A_   512
#define T_   512
#define F_   128
#define RBF_ 25
#define TBLK 128
#define NBLK (T_/TBLK)

// Precomputed y = x @ Win, [B,A,F]
__device__ __align__(16) float g_y[B_ * A_ * F_];

// ---------------- smem layout (float offsets) ----------------
// WF1P: packed B-frag float2 [kg(4)][g(128)][t4(4)][2]        4096
// RS:   [128][36]                                              4608
// H1P:  packed B-frag float2 [kg(16)][c(128)][t4(4)][2]       16384
// GTP:  packed A-frag float4 [kg(16)][pp(8)][q(8)][pos(4)][4] 16384 (reused: Wf2 plain)
#define OFF_WF1P 0
#define OFF_RS   4096
#define OFF_H1P  8704
#define OFF_GTP  25088
#define OFF_BF1  41472
#define OFF_NJ   41600
#define OFF_NK   41728
#define OFF_MSK  41856
#define OFF_GS   41984
#define OFF_PRT  42240
#define OFF_ACC  42752
#define SMEM_FLOATS 42880
#define SMEM_BYTES  (SMEM_FLOATS * 4)

#define LN2 0.69314718055994530942f

// fast shifted softplus: 2 MUFU + few FFMA; abs err ~1e-6 (<< tf32 noise)
static __device__ __forceinline__ float ssp(float v) {
    float e = __expf(-fabsf(v));
    return fmaxf(v, 0.0f) + LN2 * __log2f(1.0f + e) - LN2;
}
static __device__ __forceinline__ uint32_t f2t(float f) {
    uint32_t r;
    asm("cvt.rna.tf32.f32 %0, %1;" : "=r"(r) : "f"(f));
    return r;
}
static __device__ __forceinline__ void mma8(float* d, const uint32_t* a,
                                            uint32_t b0, uint32_t b1) {
    asm volatile(
        "mma.sync.aligned.m16n8k8.row.col.f32.tf32.tf32.f32 "
        "{%0,%1,%2,%3}, {%4,%5,%6,%7}, {%8,%9}, {%0,%1,%2,%3};"
        : "+f"(d[0]), "+f"(d[1]), "+f"(d[2]), "+f"(d[3])
        : "r"(a[0]), "r"(a[1]), "r"(a[2]), "r"(a[3]),
          "r"(b0), "r"(b1));
}

// ---------------------------------------------------------------------------
// Kernel 1: y[ba,f] = sum_i x[ba,i] * Win[i,f]
// ---------------------------------------------------------------------------
__global__ __launch_bounds__(128) void y_kernel(const float* __restrict__ x,
                                                const float* __restrict__ Win) {
    int ba = blockIdx.x, f = threadIdx.x;
    __shared__ float xs[F_];
    xs[f] = x[ba * F_ + f];
    __syncthreads();
    float acc = 0.0f;
#pragma unroll 8
    for (int i = 0; i < F_; i++) acc = fmaf(xs[i], Win[i * F_ + f], acc);
    g_y[ba * F_ + f] = acc;
}

// ---------------------------------------------------------------------------
// Main fused kernel. One CTA per (b,a). 512 threads = 16 warps.
// ---------------------------------------------------------------------------
__global__ __launch_bounds__(512, 1) void cfconv_mma(
    const float* __restrict__ r_ij,
    const float* __restrict__ mask,
    const float* __restrict__ Wf1,
    const float* __restrict__ bf1,
    const float* __restrict__ Wf2,
    const float* __restrict__ bf2,
    const float* __restrict__ Wout,
    const float* __restrict__ bout,
    const int*   __restrict__ nbr_j,
    const int*   __restrict__ nbr_k,
    float*       __restrict__ out)
{
    extern __shared__ float sm[];
    uint32_t* smu = (uint32_t*)sm;

    const int tid  = threadIdx.x;
    const int wid  = tid >> 5;
    const int lane = tid & 31;
    const int gr   = lane >> 2;
    const int t4   = lane & 3;
    const int ba   = blockIdx.x;
    const int b    = ba / A_;

    // ---- one-time loads: Wf1 in packed B-frag layout ----
    for (int i = tid; i < 32 * F_; i += 512) {
        int r = i >> 7, g = i & 127;
        float v = (r < RBF_) ? Wf1[r * F_ + g] : 0.0f;
        int kg = r >> 3, th = (r >> 2) & 1, k4 = r & 3;
        smu[OFF_WF1P + kg * 1024 + g * 8 + k4 * 2 + th] = f2t(v);
    }
    if (tid < 128) sm[OFF_BF1 + tid] = bf1[tid];
    __syncthreads();

    // stage-2 accumulator: warp (wm,wn) owns f-rows [wm*32,+32), g-cols [wn*32,+32)
    const int wm = wid & 3, wn = wid >> 2;
    const int m0 = wm * 32, n0 = wn * 32;
    float P[2][4][4];
#pragma unroll
    for (int mt = 0; mt < 2; mt++)
#pragma unroll
        for (int nt = 0; nt < 4; nt++)
#pragma unroll
            for (int j = 0; j < 4; j++) P[mt][nt][j] = 0.0f;

    // stage-2 operand base pointers (packed layouts)
    const uint32_t* gAp0 = &smu[OFF_GTP + (2 * wm * 8 + gr) * 16 + ((t4 ^ (gr & 3)) << 2)];
    const uint32_t* gAp1 = gAp0 + 128;   // pp+1
    const uint32_t* hBp  = &smu[OFF_H1P + n0 * 8 + gr * 8 + t4 * 2];

    float gsum = 0.0f;

    for (int blk = 0; blk < NBLK; blk++) {
        const uint32_t t0g = (uint32_t)ba * T_ + blk * TBLK;

        if (tid < 256) {
            // ===== warps 0-7: load R block [128t][32r] tf32 =====
#pragma unroll
            for (int i2 = 0; i2 < 16; i2++) {
                uint32_t i = tid + i2 * 256;
                uint32_t t = i >> 5, r = i & 31;
                float v = (r < RBF_) ? r_ij[(t0g + t) * RBF_ + r] : 0.0f;
                smu[OFF_RS + t * 36 + r] = f2t(v);
            }
            asm volatile("bar.sync 1, 256;" ::: "memory");

            // ===== stage 1: H1 = ssp(R @ Wf1 + bf1), packed-H1 output =====
            const int tb = wid * 16;
            const uint32_t* rA = &smu[OFF_RS + (tb + gr) * 36 + t4];
            const uint32_t* rB = &smu[OFF_RS + (tb + gr + 8) * 36 + t4];
            // packed H1 write bases: rows tb+gr -> kg=2*wid, tb+gr+8 -> kg=2*wid+1
            const uint32_t hwA = OFF_H1P + (2 * wid) * 1024 + (gr & 3) * 2 + ((gr >> 2) & 1);
            const uint32_t hwB = hwA + 1024;
#pragma unroll
            for (int half = 0; half < 2; half++) {
                const int nb = half * 64;
                const uint32_t* wB = &smu[OFF_WF1P + nb * 8 + gr * 8 + t4 * 2];
                float s1[8][4];
#pragma unroll
                for (int nt = 0; nt < 8; nt++)
#pragma unroll
                    for (int j = 0; j < 4; j++) s1[nt][j] = 0.0f;

#pragma unroll
                for (int k = 0; k < 4; k++) {
                    const int kk = k * 8;
                    uint32_t a[4];
                    a[0] = rA[kk];
                    a[1] = rB[kk];
                    a[2] = rA[kk + 4];
                    a[3] = rB[kk + 4];
#pragma unroll
                    for (int nt = 0; nt < 8; nt++) {
                        uint2 bb = *(const uint2*)&wB[k * 1024 + nt * 64];
                        mma8(s1[nt], a, bb.x, bb.y);
                    }
                }
#pragma unroll
                for (int nt = 0; nt < 8; nt++) {
                    int c = nb + nt * 8 + 2 * t4;
                    float bc0 = sm[OFF_BF1 + c];
                    float bc1 = sm[OFF_BF1 + c + 1];
                    smu[hwA + c * 8]       = f2t(ssp(s1[nt][0] + bc0));
                    smu[hwA + (c + 1) * 8] = f2t(ssp(s1[nt][1] + bc1));
                    smu[hwB + c * 8]       = f2t(ssp(s1[nt][2] + bc0));
                    smu[hwB + (c + 1) * 8] = f2t(ssp(s1[nt][3] + bc1));
                }
            }
        } else {
            // ===== warps 8-15: gather G into packed A-frag layout =====
            const int idx = tid - 256;
            const uint32_t f = idx & 127;
            const int th2 = idx >> 7;
            if (idx < 128) {
                ((int*)(sm + OFF_NJ))[idx] = nbr_j[t0g + idx];
                ((int*)(sm + OFF_NK))[idx] = nbr_k[t0g + idx];
                sm[OFF_MSK + idx]          = mask[t0g + idx];
            }
            asm volatile("bar.sync 2, 256;" ::: "memory");

            const float* yb  = g_y + (uint32_t)b * (A_ * F_) + f;
            const int*   sNj = (const int*)(sm + OFF_NJ);
            const int*   sNk = (const int*)(sm + OFF_NK);
            const float* sM  = sm + OFF_MSK;

            // packed write base for this f
            const uint32_t pp = f >> 4, pe = (f >> 3) & 1, q = f & 7;
            const uint32_t swz = f & 3;
            const uint32_t gbase = OFF_GTP + pp * 128 + q * 16 + pe;

            const int tbeg = th2 * 64;
#pragma unroll 2
            for (int tt = tbeg; tt < tbeg + 64; tt += 4) {
                const uint32_t kg = (uint32_t)tt >> 3;
                const uint32_t th = ((uint32_t)tt >> 2) & 1;
                const uint32_t wb = gbase + kg * 1024 + th * 2;
#pragma unroll
                for (int w = 0; w < 4; w++) {
                    int t = tt + w;
                    float gv = yb[(uint32_t)sNj[t] * F_]
                             * yb[(uint32_t)sNk[t] * F_] * sM[t];
                    gsum += gv;
                    smu[wb + (((uint32_t)w ^ swz) << 2)] = f2t(gv);
                }
            }
        }
        __syncthreads();

        // ===== stage 2: P += G^T @ H1 (K=128), vectorized fragment loads =====
#pragma unroll
        for (int k = 0; k < 16; k++) {
            uint4 va0 = *(const uint4*)&gAp0[k * 1024];
            uint4 va1 = *(const uint4*)&gAp1[k * 1024];
#pragma unroll
            for (int nt = 0; nt < 4; nt++) {
                uint2 bb = *(const uint2*)&hBp[k * 1024 + nt * 64];
                mma8(P[0][nt], (const uint32_t*)&va0, bb.x, bb.y);
                mma8(P[1][nt], (const uint32_t*)&va1, bb.x, bb.y);
            }
        }
        __syncthreads();
    }

    // ---- epilogue ----
    if (tid >= 256) sm[OFF_GS + tid - 256] = gsum;
    for (int i = tid; i < F_ * F_; i += 512) sm[OFF_GTP + i] = Wf2[i];
    __syncthreads();

#pragma unroll
    for (int mt = 0; mt < 2; mt++) {
        int f0 = m0 + mt * 16 + gr;
        int f1 = f0 + 8;
        float p0 = 0.0f, p1 = 0.0f;
#pragma unroll
        for (int nt = 0; nt < 4; nt++) {
            int c = n0 + nt * 8 + 2 * t4;
            p0 += P[mt][nt][0] * sm[OFF_GTP + c * F_ + f0]
                + P[mt][nt][1] * sm[OFF_GTP + (c + 1) * F_ + f0];
            p1 += P[mt][nt][2] * sm[OFF_GTP + c * F_ + f1]
                + P[mt][nt][3] * sm[OFF_GTP + (c + 1) * F_ + f1];
        }
        p0 += __shfl_xor_sync(0xFFFFFFFFu, p0, 1);
        p0 += __shfl_xor_sync(0xFFFFFFFFu, p0, 2);
        p1 += __shfl_xor_sync(0xFFFFFFFFu, p1, 1);
        p1 += __shfl_xor_sync(0xFFFFFFFFu, p1, 2);
        if (t4 == 0) {
            sm[OFF_PRT + wn * F_ + f0] = p0;
            sm[OFF_PRT + wn * F_ + f1] = p1;
        }
    }
    __syncthreads();

    if (tid < 128) {
        float acc = sm[OFF_PRT + tid]          + sm[OFF_PRT + F_ + tid]
                  + sm[OFF_PRT + 2 * F_ + tid] + sm[OFF_PRT + 3 * F_ + tid]
                  + bf2[tid] * (sm[OFF_GS + tid] + sm[OFF_GS + tid + 128]);
        sm[OFF_ACC + tid] = acc;
    }
    __syncthreads();

    if (tid < 128) {
        float o = bout[tid];
#pragma unroll 8
        for (int g = 0; g < F_; g++)
            o = fmaf(sm[OFF_ACC + g], Wout[g * F_ + tid], o);
        out[(uint32_t)ba * F_ + tid] = ssp(o);
    }
}

// ---------------------------------------------------------------------------
extern "C" void kernel_launch(void* const* d_in, const int* in_sizes, int n_in,
                              void* d_out, int out_size)
{
    const float* x     = (const float*)d_in[0];
    const float* r_ij  = (const float*)d_in[1];
    const float* mask  = (const float*)d_in[2];
    const float* Wf1   = (const float*)d_in[3];
    const float* bf1   = (const float*)d_in[4];
    const float* Wf2   = (const float*)d_in[5];
    const float* bf2   = (const float*)d_in[6];
    const float* Win   = (const float*)d_in[7];
    const float* Wout  = (const float*)d_in[8];
    const float* bout  = (const float*)d_in[9];
    const int*   nbr_j = (const int*)d_in[10];
    const int*   nbr_k = (const int*)d_in[11];
    float* out = (float*)d_out;

    cudaFuncSetAttribute(cfconv_mma,
                         cudaFuncAttributeMaxDynamicSharedMemorySize,
                         SMEM_BYTES);

    y_kernel<<<B_ * A_, 128>>>(x, Win);
    cfconv_mma<<<B_ * A_, 512, SMEM_BYTES>>>(
        r_ij, mask, Wf1, bf1, Wf2, bf2, Wout, bout, nbr_j, nbr_k, out);
}

// round 7
// speedup vs baseline: 2.0003x; 2.0003x over previous
#include <cuda_runtime.h>
#include <cstdint>

#define B_   2
#define A_   512
#define T_   512
#define F_   128
#define RBF_ 25
#define TBLK 128
#define NBLK (T_/TBLK)

// Precomputed y = x @ Win, [B,A,F]
__device__ __align__(16) float g_y[B_ * A_ * F_];

// ---------------- smem layout (float offsets) ----------------
#define OFF_WF1 0               // [32][136] tf32        4352
#define OFF_RS0 4352            // [128][36] raw f32     4608  (buffer 0)
#define OFF_RS1 8960            // [128][36] raw f32     4608  (buffer 1)
#define OFF_H1  13568           // [128][136] tf32       17408
#define OFF_GT  30976           // [128][132] tf32       16896 (reused: Wf2 plain)
#define OFF_BF1 47872           // 128
#define OFF_NJ  48000           // 2 x 128 int
#define OFF_NK  48256           // 2 x 128 int
#define OFF_MSK 48512           // 2 x 128 float
#define OFF_GS  48768           // 256
#define OFF_PRT 49024           // 4*128
#define OFF_ACC 49536           // 128
#define SMEM_FLOATS 49664
#define SMEM_BYTES  (SMEM_FLOATS * 4)

#define LN2 0.69314718055994530942f

static __device__ __forceinline__ float ssp(float v) {
    float e = __expf(-fabsf(v));
    return fmaxf(v, 0.0f) + LN2 * __log2f(1.0f + e) - LN2;
}
static __device__ __forceinline__ uint32_t f2t(float f) {
    uint32_t r;
    asm("cvt.rna.tf32.f32 %0, %1;" : "=r"(r) : "f"(f));
    return r;
}
static __device__ __forceinline__ void mma8(float* d, const uint32_t* a,
                                            const uint32_t* b) {
    asm volatile(
        "mma.sync.aligned.m16n8k8.row.col.f32.tf32.tf32.f32 "
        "{%0,%1,%2,%3}, {%4,%5,%6,%7}, {%8,%9}, {%0,%1,%2,%3};"
        : "+f"(d[0]), "+f"(d[1]), "+f"(d[2]), "+f"(d[3])
        : "r"(a[0]), "r"(a[1]), "r"(a[2]), "r"(a[3]),
          "r"(b[0]), "r"(b[1]));
}
static __device__ __forceinline__ uint32_t smem_u32(const void* p) {
    uint32_t a;
    asm("{ .reg .u64 t; cvta.to.shared.u64 t, %1; cvt.u32.u64 %0, t; }"
        : "=r"(a) : "l"(p));
    return a;
}
#define CP_ASYNC4(dst, src) \
    asm volatile("cp.async.ca.shared.global [%0], [%1], 4;" \
                 :: "r"(dst), "l"(src) : "memory")
#define CP_COMMIT() asm volatile("cp.async.commit_group;" ::: "memory")
#define CP_WAIT0()  asm volatile("cp.async.wait_group 0;" ::: "memory")

// ---------------------------------------------------------------------------
// Kernel 1: y[ba,f] = sum_i x[ba,i] * Win[i,f]
// ---------------------------------------------------------------------------
__global__ __launch_bounds__(128) void y_kernel(const float* __restrict__ x,
                                                const float* __restrict__ Win) {
    int ba = blockIdx.x, f = threadIdx.x;
    __shared__ float xs[F_];
    xs[f] = x[ba * F_ + f];
    __syncthreads();
    float acc = 0.0f;
#pragma unroll 8
    for (int i = 0; i < F_; i++) acc = fmaf(xs[i], Win[i * F_ + f], acc);
    g_y[ba * F_ + f] = acc;
}

// ---------------------------------------------------------------------------
// Prefetch block data for (t0g) into buffer par via cp.async. All 512 threads.
// ---------------------------------------------------------------------------
static __device__ __forceinline__ void issue_prefetch(
    uint32_t sb, int tid, uint32_t t0g, int par,
    const float* __restrict__ r_ij,
    const int* __restrict__ nbr_j, const int* __restrict__ nbr_k,
    const float* __restrict__ mask)
{
    const uint32_t rsb = sb + (uint32_t)(OFF_RS0 + par * 4608) * 4u;
#pragma unroll
    for (int j = 0; j < 8; j++) {
        uint32_t idx = (uint32_t)tid + j * 512;
        uint32_t t = idx >> 5, r = idx & 31;
        if (r < RBF_)
            CP_ASYNC4(rsb + (t * 36 + r) * 4, r_ij + (size_t)(t0g + t) * RBF_ + r);
    }
    if (tid < 128)
        CP_ASYNC4(sb + (OFF_NJ + par * 128 + tid) * 4, nbr_j + t0g + tid);
    else if (tid < 256)
        CP_ASYNC4(sb + (OFF_NK + par * 128 + (tid - 128)) * 4, nbr_k + t0g + (tid - 128));
    else if (tid < 384)
        CP_ASYNC4(sb + (OFF_MSK + par * 128 + (tid - 256)) * 4, mask + t0g + (tid - 256));
    CP_COMMIT();
}

// ---------------------------------------------------------------------------
// Main fused kernel. One CTA per (b,a). 512 threads = 16 warps.
// ---------------------------------------------------------------------------
__global__ __launch_bounds__(512, 1) void cfconv_mma(
    const float* __restrict__ r_ij,
    const float* __restrict__ mask,
    const float* __restrict__ Wf1,
    const float* __restrict__ bf1,
    const float* __restrict__ Wf2,
    const float* __restrict__ bf2,
    const float* __restrict__ Wout,
    const float* __restrict__ bout,
    const int*   __restrict__ nbr_j,
    const int*   __restrict__ nbr_k,
    float*       __restrict__ out)
{
    extern __shared__ float sm[];
    uint32_t* smu = (uint32_t*)sm;
    const uint32_t sb = smem_u32(sm);

    const int tid  = threadIdx.x;
    const int wid  = tid >> 5;
    const int lane = tid & 31;
    const int gr   = lane >> 2;
    const int t4   = lane & 3;
    const int ba   = blockIdx.x;
    const int b    = ba / A_;

    // zero the RS pad columns (r in [25,36)) for both buffers — never written after
    for (int i = tid; i < 2 * TBLK * 11; i += 512) {
        int buf = i / (TBLK * 11);
        int k = i - buf * (TBLK * 11);
        int t = k / 11, r = 25 + (k - t * 11);
        sm[OFF_RS0 + buf * 4608 + t * 36 + r] = 0.0f;
    }

    // prefetch block 0
    issue_prefetch(sb, tid, (uint32_t)ba * T_, 0, r_ij, nbr_j, nbr_k, mask);

    // ---- one-time loads ----
    for (int i = tid; i < 32 * F_; i += 512) {
        int k = i >> 7, g = i & 127;
        float v = (k < RBF_) ? Wf1[k * F_ + g] : 0.0f;
        smu[OFF_WF1 + k * 136 + g] = f2t(v);
    }
    if (tid < 128) sm[OFF_BF1 + tid] = bf1[tid];

    // stage-2 accumulator: warp (wm,wn) owns f-rows [wm*32,+32), g-cols [wn*32,+32)
    const int wm = wid & 3, wn = wid >> 2;
    const int m0 = wm * 32, n0 = wn * 32;
    float P[2][4][4];
#pragma unroll
    for (int mt = 0; mt < 2; mt++)
#pragma unroll
        for (int nt = 0; nt < 4; nt++)
#pragma unroll
            for (int j = 0; j < 4; j++) P[mt][nt][j] = 0.0f;

    const uint32_t* gA0 = &smu[OFF_GT + (m0 + gr) * 132 + t4];
    const uint32_t* gA1 = &smu[OFF_GT + (m0 + gr + 8) * 132 + t4];
    const uint32_t* gA2 = &smu[OFF_GT + (m0 + 16 + gr) * 132 + t4];
    const uint32_t* gA3 = &smu[OFF_GT + (m0 + 24 + gr) * 132 + t4];
    const uint32_t* hB  = &smu[OFF_H1 + t4 * 136 + n0 + gr];

    float gsum = 0.0f;

    CP_WAIT0();
    __syncthreads();    // weights + block-0 prefetch visible to all

    for (int blk = 0; blk < NBLK; blk++) {
        const int par = blk & 1;
        const uint32_t rsoff = OFF_RS0 + par * 4608;

        if (tid < 256) {
            // ===== stage 1: H1 = ssp(R @ Wf1 + bf1); R raw fp32 (HW truncates) =====
            const int tb = wid * 16;
            const uint32_t* rA = &smu[rsoff + (tb + gr) * 36 + t4];
            const uint32_t* rB = &smu[rsoff + (tb + gr + 8) * 36 + t4];
#pragma unroll
            for (int half = 0; half < 2; half++) {
                const int nb = half * 64;
                const uint32_t* wB = &smu[OFF_WF1 + t4 * 136 + nb + gr];
                float s1[8][4];
#pragma unroll
                for (int nt = 0; nt < 8; nt++)
#pragma unroll
                    for (int j = 0; j < 4; j++) s1[nt][j] = 0.0f;

#pragma unroll
                for (int k = 0; k < 4; k++) {
                    const int kk = k * 8;
                    uint32_t a[4];
                    a[0] = rA[kk];
                    a[1] = rB[kk];
                    a[2] = rA[kk + 4];
                    a[3] = rB[kk + 4];
#pragma unroll
                    for (int nt = 0; nt < 8; nt++) {
                        uint32_t bfr[2];
                        bfr[0] = wB[kk * 136 + nt * 8];
                        bfr[1] = wB[(kk + 4) * 136 + nt * 8];
                        mma8(s1[nt], a, bfr);
                    }
                }
#pragma unroll
                for (int nt = 0; nt < 8; nt++) {
                    int c = nb + nt * 8 + 2 * t4;
                    float bc0 = sm[OFF_BF1 + c];
                    float bc1 = sm[OFF_BF1 + c + 1];
                    smu[OFF_H1 + (tb + gr) * 136 + c]     = f2t(ssp(s1[nt][0] + bc0));
                    smu[OFF_H1 + (tb + gr) * 136 + c + 1] = f2t(ssp(s1[nt][1] + bc1));
                    smu[OFF_H1 + (tb + gr + 8) * 136 + c]     = f2t(ssp(s1[nt][2] + bc0));
                    smu[OFF_H1 + (tb + gr + 8) * 136 + c + 1] = f2t(ssp(s1[nt][3] + bc1));
                }
            }
        } else {
            // ===== warps 8-15: gather G^T[f][t], batched LDG (MLP 16) =====
            const int idx = tid - 256;
            const uint32_t f = idx & 127;
            const int th2 = idx >> 7;

            const float* yb  = g_y + (uint32_t)b * (A_ * F_) + f;
            const int*   sNj = (const int*)(sm + OFF_NJ + par * 128);
            const int*   sNk = (const int*)(sm + OFF_NK + par * 128);
            const float* sM  = sm + OFF_MSK + par * 128;

            const int tbeg = th2 * 64;
#pragma unroll
            for (int tt = tbeg; tt < tbeg + 64; tt += 8) {
                float vj[8], vk[8];
#pragma unroll
                for (int w = 0; w < 8; w++) {
                    vj[w] = yb[(uint32_t)sNj[tt + w] * F_];
                    vk[w] = yb[(uint32_t)sNk[tt + w] * F_];
                }
                uint4 q0, q1;
                uint32_t* g0 = (uint32_t*)&q0;
                uint32_t* g1 = (uint32_t*)&q1;
#pragma unroll
                for (int w = 0; w < 8; w++) {
                    float gv = vj[w] * vk[w] * sM[tt + w];
                    gsum += gv;
                    if (w < 4) g0[w] = f2t(gv);
                    else       g1[w - 4] = f2t(gv);
                }
                *(uint4*)&smu[OFF_GT + f * 132 + tt]     = q0;
                *(uint4*)&smu[OFF_GT + f * 132 + tt + 4] = q1;
            }
        }
        __syncthreads();

        // issue prefetch for next block while MMAs run
        if (blk + 1 < NBLK)
            issue_prefetch(sb, tid, (uint32_t)ba * T_ + (blk + 1) * TBLK,
                           par ^ 1, r_ij, nbr_j, nbr_k, mask);

        // ===== stage 2: P += G^T @ H1 (K=128), fully unrolled =====
#pragma unroll
        for (int k = 0; k < 16; k++) {
            const int kk = k * 8;
            uint32_t a[2][4];
            a[0][0] = gA0[kk];
            a[0][1] = gA1[kk];
            a[0][2] = gA0[kk + 4];
            a[0][3] = gA1[kk + 4];
            a[1][0] = gA2[kk];
            a[1][1] = gA3[kk];
            a[1][2] = gA2[kk + 4];
            a[1][3] = gA3[kk + 4];
#pragma unroll
            for (int nt = 0; nt < 4; nt++) {
                uint32_t bfr[2];
                bfr[0] = hB[kk * 136 + nt * 8];
                bfr[1] = hB[(kk + 4) * 136 + nt * 8];
                mma8(P[0][nt], a[0], bfr);
                mma8(P[1][nt], a[1], bfr);
            }
        }
        CP_WAIT0();
        __syncthreads();
    }

    // ---- epilogue ----
    if (tid >= 256) sm[OFF_GS + tid - 256] = gsum;
    for (int i = tid; i < F_ * F_; i += 512) sm[OFF_GT + i] = Wf2[i];
    __syncthreads();

#pragma unroll
    for (int mt = 0; mt < 2; mt++) {
        int f0 = m0 + mt * 16 + gr;
        int f1 = f0 + 8;
        float p0 = 0.0f, p1 = 0.0f;
#pragma unroll
        for (int nt = 0; nt < 4; nt++) {
            int c = n0 + nt * 8 + 2 * t4;
            p0 += P[mt][nt][0] * sm[OFF_GT + c * F_ + f0]
                + P[mt][nt][1] * sm[OFF_GT + (c + 1) * F_ + f0];
            p1 += P[mt][nt][2] * sm[OFF_GT + c * F_ + f1]
                + P[mt][nt][3] * sm[OFF_GT + (c + 1) * F_ + f1];
        }
        p0 += __shfl_xor_sync(0xFFFFFFFFu, p0, 1);
        p0 += __shfl_xor_sync(0xFFFFFFFFu, p0, 2);
        p1 += __shfl_xor_sync(0xFFFFFFFFu, p1, 1);
        p1 += __shfl_xor_sync(0xFFFFFFFFu, p1, 2);
        if (t4 == 0) {
            sm[OFF_PRT + wn * F_ + f0] = p0;
            sm[OFF_PRT + wn * F_ + f1] = p1;
        }
    }
    __syncthreads();

    if (tid < 128) {
        float acc = sm[OFF_PRT + tid]          + sm[OFF_PRT + F_ + tid]
                  + sm[OFF_PRT + 2 * F_ + tid] + sm[OFF_PRT + 3 * F_ + tid]
                  + bf2[tid] * (sm[OFF_GS + tid] + sm[OFF_GS + tid + 128]);
        sm[OFF_ACC + tid] = acc;
    }
    __syncthreads();

    if (tid < 128) {
        float o = bout[tid];
#pragma unroll 8
        for (int g = 0; g < F_; g++)
            o = fmaf(sm[OFF_ACC + g], Wout[g * F_ + tid], o);
        out[(uint32_t)ba * F_ + tid] = ssp(o);
    }
}

// ---------------------------------------------------------------------------
extern "C" void kernel_launch(void* const* d_in, const int* in_sizes, int n_in,
                              void* d_out, int out_size)
{
    const float* x     = (const float*)d_in[0];
    const float* r_ij  = (const float*)d_in[1];
    const float* mask  = (const float*)d_in[2];
    const float* Wf1   = (const float*)d_in[3];
    const float* bf1   = (const float*)d_in[4];
    const float* Wf2   = (const float*)d_in[5];
    const float* bf2   = (const float*)d_in[6];
    const float* Win   = (const float*)d_in[7];
    const float* Wout  = (const float*)d_in[8];
    const float* bout  = (const float*)d_in[9];
    const int*   nbr_j = (const int*)d_in[10];
    const int*   nbr_k = (const int*)d_in[11];
    float* out = (float*)d_out;

    cudaFuncSetAttribute(cfconv_mma,
                         cudaFuncAttributeMaxDynamicSharedMemorySize,
                         SMEM_BYTES);

    y_kernel<<<B_ * A_, 128>>>(x, Win);
    cfconv_mma<<<B_ * A_, 512, SMEM_BYTES>>>(
        r_ij, mask, Wf1, bf1, Wf2, bf2, Wout, bout, nbr_j, nbr_k, out);
}

// round 9
// speedup vs baseline: 2.0169x; 1.0083x over previous
#include <cuda_runtime.h>
#include <cstdint>

#define B_   2
#define A_   512
#define T_   512
#define F_   128
#define RBF_ 25
#define TBLK 64
#define NBLK (T_/TBLK)

// Precomputed y = x @ Win, [B,A,F]
__device__ __align__(16) float g_y[B_ * A_ * F_];

// ---------------- smem layout (float offsets) ----------------
// shared: Wf1 [32][136] tf32 + bf1
#define OFF_WF1 0
#define OFF_BF1 4352
// per-engine block (ESZ floats), base E = 4480 + eng*ESZ
#define ERS0 0        // [64][36] raw f32 (buf0)     2304
#define ERS1 2304     // buf1                        2304
#define EH1  4608     // [64][136] tf32  (t x g)     8704
#define EGT  13312    // [128][68] tf32  (f x t)     8704  (EH1..EGT contiguous 17408 -> Wf2 overlay)
#define ENJ  22016    // 2 x 64 int
#define ENK  22144    // 2 x 64 int
#define EMSK 22272    // 2 x 64 f32
#define EGS  22400    // 128
#define EPRT 22528    // 2*128
#define EACC 22784    // 128
#define ESZ  22912
#define SMEM_FLOATS (4480 + 2 * ESZ)
#define SMEM_BYTES  (SMEM_FLOATS * 4)

#define LN2 0.69314718055994530942f

static __device__ __forceinline__ float ssp(float v) {
    float e = __expf(-fabsf(v));
    return fmaxf(v, 0.0f) + LN2 * __log2f(1.0f + e) - LN2;
}
static __device__ __forceinline__ uint32_t f2t(float f) {
    uint32_t r;
    asm("cvt.rna.tf32.f32 %0, %1;" : "=r"(r) : "f"(f));
    return r;
}
static __device__ __forceinline__ void mma8(float* d, const uint32_t* a,
                                            uint32_t b0, uint32_t b1) {
    asm volatile(
        "mma.sync.aligned.m16n8k8.row.col.f32.tf32.tf32.f32 "
        "{%0,%1,%2,%3}, {%4,%5,%6,%7}, {%8,%9}, {%0,%1,%2,%3};"
        : "+f"(d[0]), "+f"(d[1]), "+f"(d[2]), "+f"(d[3])
        : "r"(a[0]), "r"(a[1]), "r"(a[2]), "r"(a[3]),
          "r"(b0), "r"(b1));
}
static __device__ __forceinline__ uint32_t smem_u32(const void* p) {
    uint32_t a;
    asm("{ .reg .u64 t; cvta.to.shared.u64 t, %1; cvt.u32.u64 %0, t; }"
        : "=r"(a) : "l"(p));
    return a;
}
#define CP_ASYNC4(dst, src) \
    asm volatile("cp.async.ca.shared.global [%0], [%1], 4;" \
                 :: "r"(dst), "l"(src) : "memory")
#define CP_COMMIT() asm volatile("cp.async.commit_group;" ::: "memory")
#define CP_WAIT0()  asm volatile("cp.async.wait_group 0;" ::: "memory")
#define EBAR(id)    asm volatile("bar.sync %0, 256;" :: "r"(id) : "memory")

// ---------------------------------------------------------------------------
// Kernel 1: y[ba,f] = sum_i x[ba,i] * Win[i,f]
// ---------------------------------------------------------------------------
__global__ __launch_bounds__(128) void y_kernel(const float* __restrict__ x,
                                                const float* __restrict__ Win) {
    int ba = blockIdx.x, f = threadIdx.x;
    __shared__ float xs[F_];
    xs[f] = x[ba * F_ + f];
    __syncthreads();
    float acc = 0.0f;
#pragma unroll 8
    for (int i = 0; i < F_; i++) acc = fmaf(xs[i], Win[i * F_ + f], acc);
    g_y[ba * F_ + f] = acc;
}

// ---------------------------------------------------------------------------
// Engine-scoped prefetch of one 64-triplet block into buffer par.
// ---------------------------------------------------------------------------
static __device__ __forceinline__ void issue_prefetch(
    uint32_t sbE, int te, uint32_t t0g, int par,
    const float* __restrict__ r_ij,
    const int* __restrict__ nbr_j, const int* __restrict__ nbr_k,
    const float* __restrict__ mask)
{
    const uint32_t rsb = sbE + (uint32_t)(ERS0 + par * 2304) * 4u;
#pragma unroll
    for (int j = 0; j < 8; j++) {
        uint32_t idx = (uint32_t)te + j * 256;
        uint32_t t = idx >> 5, r = idx & 31;
        if (r < RBF_)
            CP_ASYNC4(rsb + (t * 36 + r) * 4, r_ij + (size_t)(t0g + t) * RBF_ + r);
    }
    if (te < 64)
        CP_ASYNC4(sbE + (ENJ + par * 64 + te) * 4, nbr_j + t0g + te);
    else if (te < 128)
        CP_ASYNC4(sbE + (ENK + par * 64 + (te - 64)) * 4, nbr_k + t0g + (te - 64));
    else if (te < 192)
        CP_ASYNC4(sbE + (EMSK + par * 64 + (te - 128)) * 4, mask + t0g + (te - 128));
    CP_COMMIT();
}

// ---------------------------------------------------------------------------
// Dual-engine fused kernel. CTA = 512 threads = 2 independent 256-thread
// engines, each handling one (b,a) atom with engine-scoped barriers.
// ---------------------------------------------------------------------------
__global__ __launch_bounds__(512, 1) void cfconv_mma(
    const float* __restrict__ r_ij,
    const float* __restrict__ mask,
    const float* __restrict__ Wf1,
    const float* __restrict__ bf1,
    const float* __restrict__ Wf2,
    const float* __restrict__ bf2,
    const float* __restrict__ Wout,
    const float* __restrict__ bout,
    const int*   __restrict__ nbr_j,
    const int*   __restrict__ nbr_k,
    float*       __restrict__ out)
{
    extern __shared__ float sm[];
    uint32_t* smu = (uint32_t*)sm;
    const uint32_t sb = smem_u32(sm);

    const int tid   = threadIdx.x;
    const int eng   = tid >> 8;
    const int te    = tid & 255;
    const int wid_e = te >> 5;
    const int lane  = tid & 31;
    const int gr    = lane >> 2;
    const int t4    = lane & 3;
    const int ba    = blockIdx.x * 2 + eng;
    const int b     = ba / A_;
    const uint32_t E   = 4480u + (uint32_t)eng * ESZ;
    const uint32_t sbE = sb + E * 4u;
    const int bar_id = 1 + eng;

    // zero RS pad cols [25,32) for both buffers (engine-local; never rewritten)
    for (int i = te; i < 2 * TBLK * 7; i += 256) {
        int buf = i / (TBLK * 7);
        int k = i - buf * (TBLK * 7);
        int t = k / 7, r = 25 + (k - t * 7);
        sm[E + ERS0 + buf * 2304 + t * 36 + r] = 0.0f;
    }
    issue_prefetch(sbE, te, (uint32_t)ba * T_, 0, r_ij, nbr_j, nbr_k, mask);

    // CTA-wide one-time weights
    for (int i = tid; i < 32 * F_; i += 512) {
        int k = i >> 7, g = i & 127;
        float v = (k < RBF_) ? Wf1[k * F_ + g] : 0.0f;
        smu[OFF_WF1 + k * 136 + g] = f2t(v);
    }
    if (tid < 128) sm[OFF_BF1 + tid] = bf1[tid];

    // stage-2 tile per warp: f-rows [wm*32,+32), g-cols [wn*64,+64)
    const int wm = wid_e & 3, wn = wid_e >> 2;
    const int m0 = wm * 32, n0 = wn * 64;
    float P[2][8][4];
#pragma unroll
    for (int mt = 0; mt < 2; mt++)
#pragma unroll
        for (int nt = 0; nt < 8; nt++)
#pragma unroll
            for (int j = 0; j < 4; j++) P[mt][nt][j] = 0.0f;

    const uint32_t* gA0 = &smu[E + EGT + (m0 + gr) * 68 + t4];
    const uint32_t* gA1 = gA0 + 8 * 68;
    const uint32_t* gA2 = gA0 + 16 * 68;
    const uint32_t* gA3 = gA0 + 24 * 68;
    const uint32_t* hB  = &smu[E + EH1 + t4 * 136 + n0 + gr];

    float gsum = 0.0f;

    CP_WAIT0();
    __syncthreads();

    for (int blk = 0; blk < NBLK; blk++) {
        const int par = blk & 1;

        if (te < 128) {
            // ===== stage 1: H1 = ssp(R @ Wf1 + bf1), 16 rows/warp =====
            const int tb = wid_e * 16;
            const uint32_t rsO = E + ERS0 + (uint32_t)par * 2304;
            const uint32_t* rA = &smu[rsO + (tb + gr) * 36 + t4];
            const uint32_t* rB = &smu[rsO + (tb + gr + 8) * 36 + t4];
            uint32_t a[4][4];
#pragma unroll
            for (int k = 0; k < 4; k++) {
                a[k][0] = rA[k * 8];
                a[k][1] = rB[k * 8];
                a[k][2] = rA[k * 8 + 4];
                a[k][3] = rB[k * 8 + 4];
            }
            const uint32_t h0 = E + EH1 + (tb + gr) * 136;
            const uint32_t h1r = h0 + 8 * 136;
#pragma unroll
            for (int nt = 0; nt < 16; nt++) {
                float s[4] = {0.f, 0.f, 0.f, 0.f};
                const uint32_t* wB = &smu[OFF_WF1 + t4 * 136 + nt * 8 + gr];
#pragma unroll
                for (int k = 0; k < 4; k++)
                    mma8(s, a[k], wB[(k * 8) * 136], wB[(k * 8 + 4) * 136]);
                int c = nt * 8 + 2 * t4;
                float bc0 = sm[OFF_BF1 + c];
                float bc1 = sm[OFF_BF1 + c + 1];
                smu[h0 + c]      = f2t(ssp(s[0] + bc0));
                smu[h0 + c + 1]  = f2t(ssp(s[1] + bc1));
                smu[h1r + c]     = f2t(ssp(s[2] + bc0));
                smu[h1r + c + 1] = f2t(ssp(s[3] + bc1));
            }
        } else {
            // ===== gather: one thread per feature f, all 64 t's =====
            const uint32_t f = te - 128;
            const float* yb  = g_y + (uint32_t)b * (A_ * F_) + f;
            const int*   sNj = (const int*)(sm + E + ENJ + par * 64);
            const int*   sNk = (const int*)(sm + E + ENK + par * 64);
            const float* sM  = sm + E + EMSK + par * 64;
#pragma unroll
            for (int tt = 0; tt < TBLK; tt += 8) {
                float vj[8], vk[8];
#pragma unroll
                for (int w = 0; w < 8; w++) {
                    vj[w] = yb[(uint32_t)sNj[tt + w] * F_];
                    vk[w] = yb[(uint32_t)sNk[tt + w] * F_];
                }
                uint4 q0, q1;
                uint32_t* g0 = (uint32_t*)&q0;
                uint32_t* g1 = (uint32_t*)&q1;
#pragma unroll
                for (int w = 0; w < 8; w++) {
                    float gv = vj[w] * vk[w] * sM[tt + w];
                    gsum += gv;
                    if (w < 4) g0[w] = f2t(gv);
                    else       g1[w - 4] = f2t(gv);
                }
                *(uint4*)&smu[E + EGT + f * 68 + tt]     = q0;
                *(uint4*)&smu[E + EGT + f * 68 + tt + 4] = q1;
            }
        }
        EBAR(bar_id);

        if (blk + 1 < NBLK)
            issue_prefetch(sbE, te, (uint32_t)ba * T_ + (blk + 1) * TBLK,
                           par ^ 1, r_ij, nbr_j, nbr_k, mask);

        // ===== stage 2: P += G^T @ H1 (K=64), all 8 engine warps =====
#pragma unroll
        for (int k = 0; k < 8; k++) {
            const int kk = k * 8;
            uint32_t a0[4], a1[4];
            a0[0] = gA0[kk]; a0[1] = gA1[kk];
            a0[2] = gA0[kk + 4]; a0[3] = gA1[kk + 4];
            a1[0] = gA2[kk]; a1[1] = gA3[kk];
            a1[2] = gA2[kk + 4]; a1[3] = gA3[kk + 4];
#pragma unroll
            for (int nt = 0; nt < 8; nt++) {
                uint32_t b0 = hB[kk * 136 + nt * 8];
                uint32_t b1 = hB[(kk + 4) * 136 + nt * 8];
                mma8(P[0][nt], a0, b0, b1);
                mma8(P[1][nt], a1, b0, b1);
            }
        }
        CP_WAIT0();
        EBAR(bar_id);
    }

    // ---- epilogue (engine-scoped) ----
    if (te >= 128) sm[E + EGS + (te - 128)] = gsum;
    EBAR(bar_id);
    // Wf2[g][f] overlay into contiguous EH1..EGT region (17408 >= 16384)
    for (int i = te; i < F_ * F_; i += 256) sm[E + EH1 + i] = Wf2[i];
    EBAR(bar_id);

#pragma unroll
    for (int mt = 0; mt < 2; mt++) {
        int f0 = m0 + mt * 16 + gr;
        int f1 = f0 + 8;
        float p0 = 0.0f, p1 = 0.0f;
#pragma unroll
        for (int nt = 0; nt < 8; nt++) {
            int c = n0 + nt * 8 + 2 * t4;
            p0 += P[mt][nt][0] * sm[E + EH1 + c * F_ + f0]
                + P[mt][nt][1] * sm[E + EH1 + (c + 1) * F_ + f0];
            p1 += P[mt][nt][2] * sm[E + EH1 + c * F_ + f1]
                + P[mt][nt][3] * sm[E + EH1 + (c + 1) * F_ + f1];
        }
        p0 += __shfl_xor_sync(0xFFFFFFFFu, p0, 1);
        p0 += __shfl_xor_sync(0xFFFFFFFFu, p0, 2);
        p1 += __shfl_xor_sync(0xFFFFFFFFu, p1, 1);
        p1 += __shfl_xor_sync(0xFFFFFFFFu, p1, 2);
        if (t4 == 0) {
            sm[E + EPRT + wn * F_ + f0] = p0;
            sm[E + EPRT + wn * F_ + f1] = p1;
        }
    }
    EBAR(bar_id);

    if (te < 128) {
        float acc = sm[E + EPRT + te] + sm[E + EPRT + F_ + te]
                  + bf2[te] * sm[E + EGS + te];
        sm[E + EACC + te] = acc;
    }
    EBAR(bar_id);

    if (te < 128) {
        float o = bout[te];
#pragma unroll 8
        for (int g = 0; g < F_; g++)
            o = fmaf(sm[E + EACC + g], Wout[g * F_ + te], o);
        out[(uint32_t)ba * F_ + te] = ssp(o);
    }
}

// ---------------------------------------------------------------------------
extern "C" void kernel_launch(void* const* d_in, const int* in_sizes, int n_in,
                              void* d_out, int out_size)
{
    const float* x     = (const float*)d_in[0];
    const float* r_ij  = (const float*)d_in[1];
    const float* mask  = (const float*)d_in[2];
    const float* Wf1   = (const float*)d_in[3];
    const float* bf1   = (const float*)d_in[4];
    const float* Wf2   = (const float*)d_in[5];
    const float* bf2   = (const float*)d_in[6];
    const float* Win   = (const float*)d_in[7];
    const float* Wout  = (const float*)d_in[8];
    const float* bout  = (const float*)d_in[9];
    const int*   nbr_j = (const int*)d_in[10];
    const int*   nbr_k = (const int*)d_in[11];
    float* out = (float*)d_out;

    cudaFuncSetAttribute(cfconv_mma,
                         cudaFuncAttributeMaxDynamicSharedMemorySize,
                         SMEM_BYTES);

    y_kernel<<<B_ * A_, 128>>>(x, Win);
    cfconv_mma<<<B_ * A_ / 2, 512, SMEM_BYTES>>>(
        r_ij, mask, Wf1, bf1, Wf2, bf2, Wout, bout, nbr_j, nbr_k, out);
}